// round 13
// baseline (speedup 1.0000x reference)
#include <cuda_runtime.h>
#include <cuda_fp16.h>
#include <math.h>
#include <stdint.h>

#define Nn 256
#define Mm 32768
#define Dd 384
#define ALPHA 20.0f
#define STOPTHR 0.005f
#define LOG_A (-5.545177444479562f)   /* log(1/256 + 1e-30) */
#define LOG_B (-10.397207708399179f)  /* log(1/32768 + 1e-30) */
#define AA 0.00390625f
#define BB 3.0517578125e-05f
#define NEGBIG (-3.0e38f)

#define NB 128           /* persistent grid: 128 blocks x 256 threads = 32768 threads */
#define NT 256

// ---------------- device state (scratch) ----------------
__device__ float    g_logK0[(size_t)Nn * Mm];   // 33.5 MB, L2-resident
__device__ __half   g_xh[(size_t)Nn * Dd];
__device__ __half   g_xl[(size_t)Nn * Dd];
__device__ __half   g_yh[(size_t)Mm * Dd];      // 25 MB
__device__ __half   g_yl[(size_t)Mm * Dd];      // 25 MB
__device__ float    g_xn[Nn];
__device__ float    g_yn[Mm];
__device__ float    g_logu[Nn];
__device__ float    g_logv[Mm];
__device__ float    g_cumu[Nn];
__device__ float    g_cumv[Mm];
__device__ unsigned g_errbits;                  // float bits, atomicMax (vals >= 0)
__device__ volatile unsigned g_barcnt;          // grid barrier monotonic counter

// ---------------- helpers ----------------
__device__ __forceinline__ uint32_t smem_u32(const void* p) {
    uint32_t a;
    asm("{ .reg .u64 t; cvta.to.shared.u64 t, %1; cvt.u32.u64 %0, t; }" : "=r"(a) : "l"(p));
    return a;
}
__device__ __forceinline__ void cp16(uint32_t dst, const void* src) {
    asm volatile("cp.async.cg.shared.global [%0], [%1], 16;" :: "r"(dst), "l"(src));
}
#define CP_COMMIT() asm volatile("cp.async.commit_group;" ::: "memory")
#define CP_WAIT2()  asm volatile("cp.async.wait_group 2;" ::: "memory")
#define CP_WAIT1()  asm volatile("cp.async.wait_group 1;" ::: "memory")
#define CP_WAIT0()  asm volatile("cp.async.wait_group 0;" ::: "memory")

__device__ __forceinline__ void ldmx4(uint32_t& r0, uint32_t& r1, uint32_t& r2,
                                      uint32_t& r3, uint32_t addr) {
    asm volatile("ldmatrix.sync.aligned.m8n8.x4.shared.b16 {%0,%1,%2,%3}, [%4];"
                 : "=r"(r0), "=r"(r1), "=r"(r2), "=r"(r3) : "r"(addr));
}
__device__ __forceinline__ void mma16816(float* c, uint32_t a0, uint32_t a1, uint32_t a2,
                                         uint32_t a3, uint32_t b0, uint32_t b1) {
    asm volatile(
        "mma.sync.aligned.m16n8k16.row.col.f32.f16.f16.f32 "
        "{%0,%1,%2,%3}, {%4,%5,%6,%7}, {%8,%9}, {%0,%1,%2,%3};"
        : "+f"(c[0]), "+f"(c[1]), "+f"(c[2]), "+f"(c[3])
        : "r"(a0), "r"(a1), "r"(a2), "r"(a3), "r"(b0), "r"(b1));
}

// ---------------- init ----------------
__global__ void k_init(float* out) {
    int idx = blockIdx.x * blockDim.x + threadIdx.x;
    if (idx < Mm) { g_logv[idx] = 0.f; g_cumv[idx] = 0.f; }
    if (idx < Nn) { g_logu[idx] = 0.f; g_cumu[idx] = 0.f; }
    if (idx == 0) { g_errbits = 0u; g_barcnt = 0u; out[0] = 0.f; }
}

// ---------------- fused norm + fp16 hi/lo split (warp per row) ----------------
__global__ void k_prep(const float* __restrict__ src, __half* __restrict__ hi,
                       __half* __restrict__ lo, float* __restrict__ norm) {
    int row  = blockIdx.x * 8 + (threadIdx.x >> 5);
    int lane = threadIdx.x & 31;
    const float4* sp = (const float4*)(src + (size_t)row * Dd);
    uint2* hp = (uint2*)(hi + (size_t)row * Dd);
    uint2* lp = (uint2*)(lo + (size_t)row * Dd);
    float s = 0.f;
    #pragma unroll
    for (int it = 0; it < 3; it++) {
        float4 v = sp[lane + it * 32];
        s = fmaf(v.x, v.x, fmaf(v.y, v.y, fmaf(v.z, v.z, fmaf(v.w, v.w, s))));
        __half h0 = __float2half_rn(v.x), h1 = __float2half_rn(v.y);
        __half h2 = __float2half_rn(v.z), h3 = __float2half_rn(v.w);
        __half l0 = __float2half_rn(v.x - __half2float(h0));
        __half l1 = __float2half_rn(v.y - __half2float(h1));
        __half l2 = __float2half_rn(v.z - __half2float(h2));
        __half l3 = __float2half_rn(v.w - __half2float(h3));
        __half2 ph0 = __halves2half2(h0, h1), ph1 = __halves2half2(h2, h3);
        __half2 pl0 = __halves2half2(l0, l1), pl1 = __halves2half2(l2, l3);
        uint2 hw, lw;
        hw.x = *(uint32_t*)&ph0; hw.y = *(uint32_t*)&ph1;
        lw.x = *(uint32_t*)&pl0; lw.y = *(uint32_t*)&pl1;
        hp[lane + it * 32] = hw;
        lp[lane + it * 32] = lw;
    }
    #pragma unroll
    for (int o = 16; o; o >>= 1) s += __shfl_xor_sync(0xffffffffu, s, o);
    if (lane == 0) norm[row] = s;
}

// ---------------- tensor-core (mma.sync) logK0 GEMM, BK=32, 4-stage + ldmatrix ----------------
// CTA tile 128(M over Nn) x 128(N over Mm), 8 warps (2x4), warp tile 64x32.
// K: 3 passes x 12 steps of k32 (xh*yh + xh*yl + xl*yh), fp32 accumulate.
// Per step: wait -> __syncthreads -> 2 chunks of [2 B-ldmx4 + 4x(A-ldmx4 + 4 mma)] -> load(s+3).
#define ASTRIDE 40                 /* 32 data halves + 8 pad; 80 B rows, LDSM conflict-free */
#define BUFB (128 * ASTRIDE * 2)   /* bytes per buffer = 10240 */
#define STAGES 4
#define KSTEPS 36                  /* 3 passes x 12 */
#define SMEM_GEMM (STAGES * BUFB * 2)   /* 81920 B dynamic */

__device__ __forceinline__ void gemm_load(int s, int i0, int j0, uint32_t sbA,
                                          uint32_t sbB, uint32_t aoff,
                                          int lrow, int lseg) {
    int p = s / 12;
    int kk = (s % 12) * 32;
    const __half* Aarr = (p == 2) ? g_xl : g_xh;
    const __half* Barr = (p == 1) ? g_yl : g_yh;
    int b = s & 3;
    const __half* ga = Aarr + (size_t)(i0 + lrow) * Dd + kk + lseg * 16;
    const __half* gb = Barr + (size_t)(j0 + lrow) * Dd + kk + lseg * 16;
    uint32_t da = sbA + b * BUFB + aoff;
    uint32_t db = sbB + b * BUFB + aoff;
    cp16(da,      ga);
    cp16(da + 16, ga + 8);
    cp16(db,      gb);
    cp16(db + 16, gb + 8);
}

__global__ void __launch_bounds__(256) k_gemm_mma() {
    extern __shared__ __half smem[];
    int tid = threadIdx.x;
    int wid = tid >> 5, lane = tid & 31;
    int wr = wid >> 2, wc = wid & 3;          // warp grid 2x4
    int g = lane >> 2, q = lane & 3;
    int i0 = blockIdx.y * 128;                // over Nn
    int j0 = blockIdx.x * 128;                // over Mm

    uint32_t sbA = smem_u32(smem);
    uint32_t sbB = sbA + STAGES * BUFB;
    int lrow = tid >> 1;                      // 0..127
    int lseg = tid & 1;                       // 0,1 (two 32B halves-of-row each)
    uint32_t aoff = (uint32_t)(lrow * ASTRIDE + lseg * 16) * 2;

    // ldmatrix per-lane addresses (buffer-relative, chunk c adds c*32 bytes)
    uint32_t a_frag_off = (uint32_t)(((wr * 64) + (lane & 15)) * ASTRIDE
                                     + (lane >> 4) * 8) * 2;
    uint32_t b_frag_off = (uint32_t)(((wc * 32) + ((lane >> 4) * 8) + (lane & 7)) * ASTRIDE
                                     + ((lane >> 3) & 1) * 8) * 2;

    float acc[4][4][4];
    #pragma unroll
    for (int a = 0; a < 4; a++)
        #pragma unroll
        for (int b = 0; b < 4; b++)
            #pragma unroll
            for (int c = 0; c < 4; c++) acc[a][b][c] = 0.f;

    gemm_load(0, i0, j0, sbA, sbB, aoff, lrow, lseg); CP_COMMIT();
    gemm_load(1, i0, j0, sbA, sbB, aoff, lrow, lseg); CP_COMMIT();
    gemm_load(2, i0, j0, sbA, sbB, aoff, lrow, lseg); CP_COMMIT();

    #pragma unroll 1
    for (int s = 0; s < KSTEPS; s++) {
        if (s < KSTEPS - 2)      { CP_WAIT2(); }
        else if (s == KSTEPS - 2){ CP_WAIT1(); }
        else                     { CP_WAIT0(); }
        __syncthreads();                       // publish stage s to all threads

        int buf = s & 3;
        uint32_t abase = sbA + buf * BUFB + a_frag_off;
        uint32_t bbase = sbB + buf * BUFB + b_frag_off;

        #pragma unroll
        for (int c = 0; c < 2; c++) {          // two k16 chunks (k, k+16)
            uint32_t b0[4], b1[4];
            ldmx4(b0[0], b1[0], b0[1], b1[1], bbase + c * 32);
            ldmx4(b0[2], b1[2], b0[3], b1[3], bbase + 16 * ASTRIDE * 2 + c * 32);
            #pragma unroll
            for (int tm = 0; tm < 4; tm++) {
                uint32_t a0, a1, a2, a3;
                ldmx4(a0, a1, a2, a3, abase + tm * (16 * ASTRIDE * 2) + c * 32);
                #pragma unroll
                for (int tn = 0; tn < 4; tn++)
                    mma16816(acc[tm][tn], a0, a1, a2, a3, b0[tn], b1[tn]);
            }
        }

        if (s + 3 < KSTEPS) {
            gemm_load(s + 3, i0, j0, sbA, sbB, aoff, lrow, lseg);
            CP_COMMIT();
        }
    }

    // ---- epilogue: logK0 = 2a*dot - a*(xn_i + yn_j) ----
    #pragma unroll
    for (int tm = 0; tm < 4; tm++) {
        int r0 = i0 + wr * 64 + tm * 16 + g;
        float xn0 = g_xn[r0], xn1 = g_xn[r0 + 8];
        #pragma unroll
        for (int tn = 0; tn < 4; tn++) {
            int cb = j0 + wc * 32 + tn * 8 + q * 2;
            float yn0 = g_yn[cb], yn1 = g_yn[cb + 1];
            float2 o0, o1;
            o0.x = fmaf(2.f * ALPHA, acc[tm][tn][0], -ALPHA * (xn0 + yn0));
            o0.y = fmaf(2.f * ALPHA, acc[tm][tn][1], -ALPHA * (xn0 + yn1));
            o1.x = fmaf(2.f * ALPHA, acc[tm][tn][2], -ALPHA * (xn1 + yn0));
            o1.y = fmaf(2.f * ALPHA, acc[tm][tn][3], -ALPHA * (xn1 + yn1));
            *(float2*)(g_logK0 + (size_t)r0 * Mm + cb)       = o0;
            *(float2*)(g_logK0 + (size_t)(r0 + 8) * Mm + cb) = o1;
        }
    }
}

// ============ persistent Sinkhorn (+ fused transp/loss) ============

__device__ __forceinline__ void gridbar(unsigned& epoch) {
    epoch += NB;
    __syncthreads();
    if (threadIdx.x == 0) {
        __threadfence();
        atomicAdd((unsigned*)&g_barcnt, 1u);
        while (g_barcnt < epoch) { }
        __threadfence();
    }
    __syncthreads();
}

// logv <- LOG_B - lse_i(logK0 + logu)
__device__ __forceinline__ void colpass(float* su) {
    int tid = threadIdx.x;
    su[tid] = g_logu[tid];
    __syncthreads();
    int j = blockIdx.x * NT + tid;
    const float* col = g_logK0 + j;
    float mx = NEGBIG;
    #pragma unroll 16
    for (int i = 0; i < Nn; i++)
        mx = fmaxf(mx, col[(size_t)i * Mm] + su[i]);
    float s = 0.f;
    #pragma unroll 16
    for (int i = 0; i < Nn; i++)
        s += __expf(col[(size_t)i * Mm] + su[i] - mx);
    g_logv[j] = LOG_B - (mx + logf(s));
    __syncthreads();
}

// logu <- LOG_A - lse_j(logK0 + logv)   (2 rows per block, float4 + unroll)
__device__ __forceinline__ void rowpass(float* red) {
    int tid = threadIdx.x;
    int i0 = blockIdx.x * 2;
    const float4* r0 = (const float4*)(g_logK0 + (size_t)i0 * Mm);
    const float4* r1 = (const float4*)(g_logK0 + (size_t)(i0 + 1) * Mm);
    const float4* vv = (const float4*)g_logv;
    const int NV = Mm / 4;                    // 8192 float4 per row

    float mx0 = NEGBIG, mx1 = NEGBIG;
    #pragma unroll 8
    for (int j = tid; j < NV; j += NT) {
        float4 v = vv[j], a = r0[j], b = r1[j];
        mx0 = fmaxf(mx0, fmaxf(fmaxf(a.x + v.x, a.y + v.y), fmaxf(a.z + v.z, a.w + v.w)));
        mx1 = fmaxf(mx1, fmaxf(fmaxf(b.x + v.x, b.y + v.y), fmaxf(b.z + v.z, b.w + v.w)));
    }
    #pragma unroll
    for (int o = 16; o; o >>= 1) {
        mx0 = fmaxf(mx0, __shfl_xor_sync(0xffffffffu, mx0, o));
        mx1 = fmaxf(mx1, __shfl_xor_sync(0xffffffffu, mx1, o));
    }
    if ((tid & 31) == 0) { red[tid >> 5] = mx0; red[8 + (tid >> 5)] = mx1; }
    __syncthreads();
    float MX0 = red[0], MX1 = red[8];
    #pragma unroll
    for (int w = 1; w < 8; w++) { MX0 = fmaxf(MX0, red[w]); MX1 = fmaxf(MX1, red[8 + w]); }
    __syncthreads();

    float s0 = 0.f, s1 = 0.f;
    #pragma unroll 8
    for (int j = tid; j < NV; j += NT) {
        float4 v = vv[j], a = r0[j], b = r1[j];
        s0 += __expf(a.x + v.x - MX0) + __expf(a.y + v.y - MX0)
            + __expf(a.z + v.z - MX0) + __expf(a.w + v.w - MX0);
        s1 += __expf(b.x + v.x - MX1) + __expf(b.y + v.y - MX1)
            + __expf(b.z + v.z - MX1) + __expf(b.w + v.w - MX1);
    }
    #pragma unroll
    for (int o = 16; o; o >>= 1) {
        s0 += __shfl_xor_sync(0xffffffffu, s0, o);
        s1 += __shfl_xor_sync(0xffffffffu, s1, o);
    }
    if ((tid & 31) == 0) { red[tid >> 5] = s0; red[8 + (tid >> 5)] = s1; }
    __syncthreads();
    if (tid == 0) {
        float S0 = 0.f, S1 = 0.f;
        #pragma unroll
        for (int w = 0; w < 8; w++) { S0 += red[w]; S1 += red[8 + w]; }
        g_logu[i0]     = LOG_A - (MX0 + logf(S0));
        g_logu[i0 + 1] = LOG_A - (MX1 + logf(S1));
    }
    __syncthreads();
}

// Column-marginal error pass fused with speculative transp + loss partial.
__device__ __forceinline__ float colerr_transp(float* su, float* out, int do_err) {
    int tid = threadIdx.x;
    su[tid] = g_cumu[tid] + g_logu[tid];
    __syncthreads();
    int j = blockIdx.x * NT + tid;
    const float* col = g_logK0 + j;
    float sv = g_cumv[j] + g_logv[j];

    float mx = NEGBIG;
    #pragma unroll 16
    for (int i = 0; i < Nn; i++)
        mx = fmaxf(mx, col[(size_t)i * Mm] + su[i]);
    float scale = __expf(mx + sv);
    float s = 0.f, part = 0.f;
    #pragma unroll 8
    for (int i = 0; i < Nn; i++) {
        float v = col[(size_t)i * Mm] + su[i];
        float e = __expf(v - mx);
        s += e;
        float tr = e * scale;
        out[1 + (size_t)i * Mm + j] = tr;
        part = fmaf(tr, v - su[i], part);       // t * logK0
    }
    if (do_err) {
        float diff = fabsf(expf(sv + mx + logf(s)) - BB);
        #pragma unroll
        for (int o = 16; o; o >>= 1)
            diff = fmaxf(diff, __shfl_xor_sync(0xffffffffu, diff, o));
        if ((tid & 31) == 0) atomicMax(&g_errbits, __float_as_uint(diff));
    }
    __syncthreads();
    return part * (-1.f / ALPHA);
}

__global__ void __launch_bounds__(NT, 1) k_sink(float* out) {
    __shared__ float su[Nn];
    __shared__ float red[16];
    unsigned epoch = 0;
    int tid = threadIdx.x;
    int gtid = blockIdx.x * NT + tid;
    float part = 0.f;
    int conv = 0;

    for (int t = 1; t <= 100; t++) {
        colpass(su);
        gridbar(epoch);
        rowpass(red);
        gridbar(epoch);
        if (t % 50 == 1) {
            part = colerr_transp(su, out, 1);       // speculative transp + err
            gridbar(epoch);
            conv = (__uint_as_float(*(volatile unsigned*)&g_errbits) <= STOPTHR);
            if (conv) break;
            g_cumv[gtid] += g_logv[gtid]; g_logv[gtid] = 0.f;
            if (gtid < Nn) { g_cumu[gtid] += g_logu[gtid]; g_logu[gtid] = 0.f; }
            if (gtid == 0) g_errbits = 0u;
            gridbar(epoch);
        }
    }
    if (!conv)
        part = colerr_transp(su, out, 0);           // final state transp

    #pragma unroll
    for (int o = 16; o; o >>= 1) part += __shfl_xor_sync(0xffffffffu, part, o);
    if ((tid & 31) == 0) red[tid >> 5] = part;
    __syncthreads();
    if (tid == 0) {
        float S = 0.f;
        #pragma unroll
        for (int w = 0; w < 8; w++) S += red[w];
        atomicAdd(out, S);
    }
}

// ---------------- launch ----------------
extern "C" void kernel_launch(void* const* d_in, const int* in_sizes, int n_in,
                              void* d_out, int out_size) {
    const float* x = (const float*)d_in[0];   // [256, 384]
    const float* y = (const float*)d_in[1];   // [32768, 384]
    float* out = (float*)d_out;               // [0]=loss, [1..]=transp

    __half *xh, *xl, *yh, *yl;
    float *xn, *yn;
    cudaGetSymbolAddress((void**)&xh, g_xh);
    cudaGetSymbolAddress((void**)&xl, g_xl);
    cudaGetSymbolAddress((void**)&yh, g_yh);
    cudaGetSymbolAddress((void**)&yl, g_yl);
    cudaGetSymbolAddress((void**)&xn, g_xn);
    cudaGetSymbolAddress((void**)&yn, g_yn);

    cudaFuncSetAttribute(k_gemm_mma, cudaFuncAttributeMaxDynamicSharedMemorySize,
                         SMEM_GEMM);

    k_init<<<(Mm + 255) / 256, 256>>>(out);
    k_prep<<<Nn / 8, 256>>>(x, xh, xl, xn);
    k_prep<<<Mm / 8, 256>>>(y, yh, yl, yn);
    k_gemm_mma<<<dim3(Mm / 128, Nn / 128), 256, SMEM_GEMM>>>();
    k_sink<<<NB, NT>>>(out);
}

// round 15
// speedup vs baseline: 1.2006x; 1.2006x over previous
#include <cuda_runtime.h>
#include <cuda_fp16.h>
#include <math.h>
#include <stdint.h>

#define Nn 256
#define Mm 32768
#define Dd 384
#define ALPHA 20.0f
#define STOPTHR 0.005f
#define LOG_A (-5.545177444479562f)   /* log(1/256 + 1e-30) */
#define LOG_B (-10.397207708399179f)  /* log(1/32768 + 1e-30) */
#define AA 0.00390625f
#define BB 3.0517578125e-05f
#define NEGBIG (-3.0e38f)

#define NB 128           /* persistent grid: 128 blocks x 256 threads = 32768 threads */
#define NT 256

// ---------------- device state (scratch) ----------------
__device__ float    g_logK0[(size_t)Nn * Mm];   // 33.5 MB, L2-resident
__device__ __half   g_xh[(size_t)Nn * Dd];
__device__ __half   g_xl[(size_t)Nn * Dd];
__device__ __half   g_yh[(size_t)Mm * Dd];      // 25 MB
__device__ __half   g_yl[(size_t)Mm * Dd];      // 25 MB
__device__ float    g_xn[Nn];
__device__ float    g_yn[Mm];
__device__ float    g_logu[Nn];
__device__ float    g_logv[Mm];
__device__ float    g_cumu[Nn];
__device__ float    g_cumv[Mm];
__device__ unsigned g_errbits;                  // float bits, atomicMax (vals >= 0)
__device__ volatile unsigned g_barcnt;          // grid barrier monotonic counter

// ---------------- helpers ----------------
__device__ __forceinline__ uint32_t smem_u32(const void* p) {
    uint32_t a;
    asm("{ .reg .u64 t; cvta.to.shared.u64 t, %1; cvt.u32.u64 %0, t; }" : "=r"(a) : "l"(p));
    return a;
}
__device__ __forceinline__ void cp16(uint32_t dst, const void* src) {
    asm volatile("cp.async.cg.shared.global [%0], [%1], 16;" :: "r"(dst), "l"(src));
}
#define CP_COMMIT() asm volatile("cp.async.commit_group;" ::: "memory")
#define CP_WAIT2()  asm volatile("cp.async.wait_group 2;" ::: "memory")
#define CP_WAIT1()  asm volatile("cp.async.wait_group 1;" ::: "memory")
#define CP_WAIT0()  asm volatile("cp.async.wait_group 0;" ::: "memory")

__device__ __forceinline__ void ldmx4(uint32_t& r0, uint32_t& r1, uint32_t& r2,
                                      uint32_t& r3, uint32_t addr) {
    asm volatile("ldmatrix.sync.aligned.m8n8.x4.shared.b16 {%0,%1,%2,%3}, [%4];"
                 : "=r"(r0), "=r"(r1), "=r"(r2), "=r"(r3) : "r"(addr));
}
__device__ __forceinline__ void mma16816(float* c, uint32_t a0, uint32_t a1, uint32_t a2,
                                         uint32_t a3, uint32_t b0, uint32_t b1) {
    asm volatile(
        "mma.sync.aligned.m16n8k16.row.col.f32.f16.f16.f32 "
        "{%0,%1,%2,%3}, {%4,%5,%6,%7}, {%8,%9}, {%0,%1,%2,%3};"
        : "+f"(c[0]), "+f"(c[1]), "+f"(c[2]), "+f"(c[3])
        : "r"(a0), "r"(a1), "r"(a2), "r"(a3), "r"(b0), "r"(b1));
}

// ---------------- init ----------------
__global__ void k_init(float* out) {
    int idx = blockIdx.x * blockDim.x + threadIdx.x;
    if (idx < Mm) { g_logv[idx] = 0.f; g_cumv[idx] = 0.f; }
    if (idx < Nn) { g_logu[idx] = 0.f; g_cumu[idx] = 0.f; }
    if (idx == 0) { g_errbits = 0u; g_barcnt = 0u; out[0] = 0.f; }
}

// ---------------- fused norm + fp16 hi/lo split (warp per row) ----------------
__global__ void k_prep(const float* __restrict__ src, __half* __restrict__ hi,
                       __half* __restrict__ lo, float* __restrict__ norm) {
    int row  = blockIdx.x * 8 + (threadIdx.x >> 5);
    int lane = threadIdx.x & 31;
    const float4* sp = (const float4*)(src + (size_t)row * Dd);
    uint2* hp = (uint2*)(hi + (size_t)row * Dd);
    uint2* lp = (uint2*)(lo + (size_t)row * Dd);
    float s = 0.f;
    #pragma unroll
    for (int it = 0; it < 3; it++) {
        float4 v = sp[lane + it * 32];
        s = fmaf(v.x, v.x, fmaf(v.y, v.y, fmaf(v.z, v.z, fmaf(v.w, v.w, s))));
        __half h0 = __float2half_rn(v.x), h1 = __float2half_rn(v.y);
        __half h2 = __float2half_rn(v.z), h3 = __float2half_rn(v.w);
        __half l0 = __float2half_rn(v.x - __half2float(h0));
        __half l1 = __float2half_rn(v.y - __half2float(h1));
        __half l2 = __float2half_rn(v.z - __half2float(h2));
        __half l3 = __float2half_rn(v.w - __half2float(h3));
        __half2 ph0 = __halves2half2(h0, h1), ph1 = __halves2half2(h2, h3);
        __half2 pl0 = __halves2half2(l0, l1), pl1 = __halves2half2(l2, l3);
        uint2 hw, lw;
        hw.x = *(uint32_t*)&ph0; hw.y = *(uint32_t*)&ph1;
        lw.x = *(uint32_t*)&pl0; lw.y = *(uint32_t*)&pl1;
        hp[lane + it * 32] = hw;
        lp[lane + it * 32] = lw;
    }
    #pragma unroll
    for (int o = 16; o; o >>= 1) s += __shfl_xor_sync(0xffffffffu, s, o);
    if (lane == 0) norm[row] = s;
}

// ---------------- tensor-core (mma.sync) logK0 GEMM, 4-stage + ldmatrix (round-12) ----------------
#define ASTRIDE 24
#define BUFB (128 * ASTRIDE * 2)   /* bytes per buffer = 6144 */
#define STAGES 4
#define KSTEPS 72

__device__ __forceinline__ void gemm_load(int s, int i0, int j0, uint32_t sbA,
                                          uint32_t sbB, uint32_t aoff,
                                          int lrow, int lseg) {
    int p = s / 24;
    int kk = (s % 24) * 16;
    const __half* Aarr = (p == 2) ? g_xl : g_xh;
    const __half* Barr = (p == 1) ? g_yl : g_yh;
    int b = s % STAGES;
    cp16(sbA + b * BUFB + aoff, Aarr + (size_t)(i0 + lrow) * Dd + kk + lseg * 8);
    cp16(sbB + b * BUFB + aoff, Barr + (size_t)(j0 + lrow) * Dd + kk + lseg * 8);
}

__global__ void __launch_bounds__(256) k_gemm_mma() {
    __shared__ __half As[STAGES][128 * ASTRIDE];
    __shared__ __half Bs[STAGES][128 * ASTRIDE];
    int tid = threadIdx.x;
    int wid = tid >> 5, lane = tid & 31;
    int wr = wid >> 2, wc = wid & 3;          // warp grid 2x4
    int g = lane >> 2, q = lane & 3;
    int i0 = blockIdx.y * 128;                // over Nn
    int j0 = blockIdx.x * 128;                // over Mm

    uint32_t sbA = smem_u32(As);
    uint32_t sbB = smem_u32(Bs);
    int lrow = tid >> 1;                      // 0..127
    int lseg = tid & 1;
    uint32_t aoff = (uint32_t)(lrow * ASTRIDE + lseg * 8) * 2;

    uint32_t a_frag_off = (uint32_t)(((wr * 64) + (lane & 15)) * ASTRIDE
                                     + (lane >> 4) * 8) * 2;
    uint32_t b_frag_off = (uint32_t)(((wc * 32) + ((lane >> 4) * 8) + (lane & 7)) * ASTRIDE
                                     + ((lane >> 3) & 1) * 8) * 2;

    float acc[4][4][4];
    #pragma unroll
    for (int a = 0; a < 4; a++)
        #pragma unroll
        for (int b = 0; b < 4; b++)
            #pragma unroll
            for (int c = 0; c < 4; c++) acc[a][b][c] = 0.f;

    gemm_load(0, i0, j0, sbA, sbB, aoff, lrow, lseg); CP_COMMIT();
    gemm_load(1, i0, j0, sbA, sbB, aoff, lrow, lseg); CP_COMMIT();
    gemm_load(2, i0, j0, sbA, sbB, aoff, lrow, lseg); CP_COMMIT();

    #pragma unroll 1
    for (int s = 0; s < KSTEPS; s++) {
        if (s < KSTEPS - 2)      { CP_WAIT2(); }
        else if (s == KSTEPS - 2){ CP_WAIT1(); }
        else                     { CP_WAIT0(); }
        __syncthreads();

        int buf = s % STAGES;
        uint32_t abase = sbA + buf * BUFB + a_frag_off;
        uint32_t bbase = sbB + buf * BUFB + b_frag_off;

        uint32_t b0[4], b1[4];
        ldmx4(b0[0], b1[0], b0[1], b1[1], bbase);
        ldmx4(b0[2], b1[2], b0[3], b1[3], bbase + 16 * ASTRIDE * 2);

        #pragma unroll
        for (int tm = 0; tm < 4; tm++) {
            uint32_t a0, a1, a2, a3;
            ldmx4(a0, a1, a2, a3, abase + tm * (16 * ASTRIDE * 2));
            #pragma unroll
            for (int tn = 0; tn < 4; tn++)
                mma16816(acc[tm][tn], a0, a1, a2, a3, b0[tn], b1[tn]);
        }

        if (s + 3 < KSTEPS) {
            gemm_load(s + 3, i0, j0, sbA, sbB, aoff, lrow, lseg);
            CP_COMMIT();
        }
    }

    #pragma unroll
    for (int tm = 0; tm < 4; tm++) {
        int r0 = i0 + wr * 64 + tm * 16 + g;
        float xn0 = g_xn[r0], xn1 = g_xn[r0 + 8];
        #pragma unroll
        for (int tn = 0; tn < 4; tn++) {
            int cb = j0 + wc * 32 + tn * 8 + q * 2;
            float yn0 = g_yn[cb], yn1 = g_yn[cb + 1];
            float2 o0, o1;
            o0.x = fmaf(2.f * ALPHA, acc[tm][tn][0], -ALPHA * (xn0 + yn0));
            o0.y = fmaf(2.f * ALPHA, acc[tm][tn][1], -ALPHA * (xn0 + yn1));
            o1.x = fmaf(2.f * ALPHA, acc[tm][tn][2], -ALPHA * (xn1 + yn0));
            o1.y = fmaf(2.f * ALPHA, acc[tm][tn][3], -ALPHA * (xn1 + yn1));
            *(float2*)(g_logK0 + (size_t)r0 * Mm + cb)       = o0;
            *(float2*)(g_logK0 + (size_t)(r0 + 8) * Mm + cb) = o1;
        }
    }
}

// ============ persistent Sinkhorn (+ fused transp/loss) ============

__device__ __forceinline__ void gridbar(unsigned& epoch) {
    epoch += NB;
    __syncthreads();
    if (threadIdx.x == 0) {
        __threadfence();
        atomicAdd((unsigned*)&g_barcnt, 1u);
        while (g_barcnt < epoch) { }
        __threadfence();
    }
    __syncthreads();
}

#define SHFL_MAX4(m, o) do { \
    m.x = fmaxf(m.x, __shfl_xor_sync(0xffffffffu, m.x, o)); \
    m.y = fmaxf(m.y, __shfl_xor_sync(0xffffffffu, m.y, o)); \
    m.z = fmaxf(m.z, __shfl_xor_sync(0xffffffffu, m.z, o)); \
    m.w = fmaxf(m.w, __shfl_xor_sync(0xffffffffu, m.w, o)); } while (0)
#define SHFL_ADD4(m, o) do { \
    m.x += __shfl_xor_sync(0xffffffffu, m.x, o); \
    m.y += __shfl_xor_sync(0xffffffffu, m.y, o); \
    m.z += __shfl_xor_sync(0xffffffffu, m.z, o); \
    m.w += __shfl_xor_sync(0xffffffffu, m.w, o); } while (0)

// logv <- LOG_B - lse_i(logK0 + logu)
// Vectorized: 4 lanes share column-group cg (4 cols, float4); lane p handles
// rows p*64..p*64+63; cross-lane shfl reduce over xor 1,2.
__device__ __forceinline__ void colpass(float* su) {
    int tid = threadIdx.x;
    su[tid] = g_logu[tid];
    __syncthreads();
    int g = blockIdx.x * NT + tid;
    int cg = g >> 2, p = g & 3;
    const float4* col = (const float4*)g_logK0 + cg;
    int ibase = p * 64;

    float4 mx = {NEGBIG, NEGBIG, NEGBIG, NEGBIG};
    #pragma unroll 8
    for (int ii = 0; ii < 64; ii++) {
        float4 v = col[(size_t)(ibase + ii) * (Mm / 4)];
        float u = su[ibase + ii];
        mx.x = fmaxf(mx.x, v.x + u); mx.y = fmaxf(mx.y, v.y + u);
        mx.z = fmaxf(mx.z, v.z + u); mx.w = fmaxf(mx.w, v.w + u);
    }
    SHFL_MAX4(mx, 1); SHFL_MAX4(mx, 2);

    float4 s = {0.f, 0.f, 0.f, 0.f};
    #pragma unroll 8
    for (int ii = 0; ii < 64; ii++) {
        float4 v = col[(size_t)(ibase + ii) * (Mm / 4)];
        float u = su[ibase + ii];
        s.x += __expf(v.x + u - mx.x); s.y += __expf(v.y + u - mx.y);
        s.z += __expf(v.z + u - mx.z); s.w += __expf(v.w + u - mx.w);
    }
    SHFL_ADD4(s, 1); SHFL_ADD4(s, 2);

    if (p == 0) {
        float4 o;
        o.x = LOG_B - (mx.x + logf(s.x));
        o.y = LOG_B - (mx.y + logf(s.y));
        o.z = LOG_B - (mx.z + logf(s.z));
        o.w = LOG_B - (mx.w + logf(s.w));
        ((float4*)g_logv)[cg] = o;
    }
    __syncthreads();
}

// logu <- LOG_A - lse_j(logK0 + logv)   (2 rows per block, float4 + unroll)
__device__ __forceinline__ void rowpass(float* red) {
    int tid = threadIdx.x;
    int i0 = blockIdx.x * 2;
    const float4* r0 = (const float4*)(g_logK0 + (size_t)i0 * Mm);
    const float4* r1 = (const float4*)(g_logK0 + (size_t)(i0 + 1) * Mm);
    const float4* vv = (const float4*)g_logv;
    const int NV = Mm / 4;

    float mx0 = NEGBIG, mx1 = NEGBIG;
    #pragma unroll 8
    for (int j = tid; j < NV; j += NT) {
        float4 v = vv[j], a = r0[j], b = r1[j];
        mx0 = fmaxf(mx0, fmaxf(fmaxf(a.x + v.x, a.y + v.y), fmaxf(a.z + v.z, a.w + v.w)));
        mx1 = fmaxf(mx1, fmaxf(fmaxf(b.x + v.x, b.y + v.y), fmaxf(b.z + v.z, b.w + v.w)));
    }
    #pragma unroll
    for (int o = 16; o; o >>= 1) {
        mx0 = fmaxf(mx0, __shfl_xor_sync(0xffffffffu, mx0, o));
        mx1 = fmaxf(mx1, __shfl_xor_sync(0xffffffffu, mx1, o));
    }
    if ((tid & 31) == 0) { red[tid >> 5] = mx0; red[8 + (tid >> 5)] = mx1; }
    __syncthreads();
    float MX0 = red[0], MX1 = red[8];
    #pragma unroll
    for (int w = 1; w < 8; w++) { MX0 = fmaxf(MX0, red[w]); MX1 = fmaxf(MX1, red[8 + w]); }
    __syncthreads();

    float s0 = 0.f, s1 = 0.f;
    #pragma unroll 8
    for (int j = tid; j < NV; j += NT) {
        float4 v = vv[j], a = r0[j], b = r1[j];
        s0 += __expf(a.x + v.x - MX0) + __expf(a.y + v.y - MX0)
            + __expf(a.z + v.z - MX0) + __expf(a.w + v.w - MX0);
        s1 += __expf(b.x + v.x - MX1) + __expf(b.y + v.y - MX1)
            + __expf(b.z + v.z - MX1) + __expf(b.w + v.w - MX1);
    }
    #pragma unroll
    for (int o = 16; o; o >>= 1) {
        s0 += __shfl_xor_sync(0xffffffffu, s0, o);
        s1 += __shfl_xor_sync(0xffffffffu, s1, o);
    }
    if ((tid & 31) == 0) { red[tid >> 5] = s0; red[8 + (tid >> 5)] = s1; }
    __syncthreads();
    if (tid == 0) {
        float S0 = 0.f, S1 = 0.f;
        #pragma unroll
        for (int w = 0; w < 8; w++) { S0 += red[w]; S1 += red[8 + w]; }
        g_logu[i0]     = LOG_A - (MX0 + logf(S0));
        g_logu[i0 + 1] = LOG_A - (MX1 + logf(S1));
    }
    __syncthreads();
}

// Column-marginal error + speculative transp + loss, vectorized loads.
// transp stores are SCALAR: out+1 is only 4-byte aligned (out[0] = loss).
__device__ __forceinline__ float colerr_transp(float* su, float* out, int do_err) {
    int tid = threadIdx.x;
    su[tid] = g_cumu[tid] + g_logu[tid];
    __syncthreads();
    int g = blockIdx.x * NT + tid;
    int cg = g >> 2, p = g & 3;
    const float4* col = (const float4*)g_logK0 + cg;
    float* outp = out + 1 + cg * 4;
    int ibase = p * 64;

    float4 cv = ((const float4*)g_cumv)[cg];
    float4 lv = ((const float4*)g_logv)[cg];
    float4 sv;
    sv.x = cv.x + lv.x; sv.y = cv.y + lv.y; sv.z = cv.z + lv.z; sv.w = cv.w + lv.w;

    float4 mx = {NEGBIG, NEGBIG, NEGBIG, NEGBIG};
    #pragma unroll 8
    for (int ii = 0; ii < 64; ii++) {
        float4 v = col[(size_t)(ibase + ii) * (Mm / 4)];
        float u = su[ibase + ii];
        mx.x = fmaxf(mx.x, v.x + u); mx.y = fmaxf(mx.y, v.y + u);
        mx.z = fmaxf(mx.z, v.z + u); mx.w = fmaxf(mx.w, v.w + u);
    }
    SHFL_MAX4(mx, 1); SHFL_MAX4(mx, 2);

    float4 scale;
    scale.x = __expf(mx.x + sv.x); scale.y = __expf(mx.y + sv.y);
    scale.z = __expf(mx.z + sv.z); scale.w = __expf(mx.w + sv.w);

    float4 s = {0.f, 0.f, 0.f, 0.f};
    float part = 0.f;
    #pragma unroll 4
    for (int ii = 0; ii < 64; ii++) {
        float4 v = col[(size_t)(ibase + ii) * (Mm / 4)];
        float u = su[ibase + ii];
        float4 e, tr;
        e.x = __expf(v.x + u - mx.x); e.y = __expf(v.y + u - mx.y);
        e.z = __expf(v.z + u - mx.z); e.w = __expf(v.w + u - mx.w);
        s.x += e.x; s.y += e.y; s.z += e.z; s.w += e.w;
        tr.x = e.x * scale.x; tr.y = e.y * scale.y;
        tr.z = e.z * scale.z; tr.w = e.w * scale.w;
        float* op = outp + (size_t)(ibase + ii) * Mm;
        op[0] = tr.x; op[1] = tr.y; op[2] = tr.z; op[3] = tr.w;
        part = fmaf(tr.x, v.x, fmaf(tr.y, v.y, fmaf(tr.z, v.z, fmaf(tr.w, v.w, part))));
    }
    SHFL_ADD4(s, 1); SHFL_ADD4(s, 2);

    if (do_err) {
        float d = fmaxf(fmaxf(fabsf(expf(sv.x + mx.x + logf(s.x)) - BB),
                              fabsf(expf(sv.y + mx.y + logf(s.y)) - BB)),
                        fmaxf(fabsf(expf(sv.z + mx.z + logf(s.z)) - BB),
                              fabsf(expf(sv.w + mx.w + logf(s.w)) - BB)));
        #pragma unroll
        for (int o = 16; o; o >>= 1)
            d = fmaxf(d, __shfl_xor_sync(0xffffffffu, d, o));
        if ((tid & 31) == 0) atomicMax(&g_errbits, __float_as_uint(d));
    }
    __syncthreads();
    return part * (-1.f / ALPHA);
}

__global__ void __launch_bounds__(NT, 1) k_sink(float* out) {
    __shared__ float su[Nn];
    __shared__ float red[16];
    unsigned epoch = 0;
    int tid = threadIdx.x;
    int gtid = blockIdx.x * NT + tid;
    float part = 0.f;
    int conv = 0;

    for (int t = 1; t <= 100; t++) {
        colpass(su);
        gridbar(epoch);
        rowpass(red);
        gridbar(epoch);
        if (t % 50 == 1) {
            part = colerr_transp(su, out, 1);       // speculative transp + err
            gridbar(epoch);
            conv = (__uint_as_float(*(volatile unsigned*)&g_errbits) <= STOPTHR);
            if (conv) break;
            g_cumv[gtid] += g_logv[gtid]; g_logv[gtid] = 0.f;
            if (gtid < Nn) { g_cumu[gtid] += g_logu[gtid]; g_logu[gtid] = 0.f; }
            if (gtid == 0) g_errbits = 0u;
            gridbar(epoch);
        }
    }
    if (!conv)
        part = colerr_transp(su, out, 0);           // final state transp

    #pragma unroll
    for (int o = 16; o; o >>= 1) part += __shfl_xor_sync(0xffffffffu, part, o);
    if ((tid & 31) == 0) red[tid >> 5] = part;
    __syncthreads();
    if (tid == 0) {
        float S = 0.f;
        #pragma unroll
        for (int w = 0; w < 8; w++) S += red[w];
        atomicAdd(out, S);
    }
}

// ---------------- launch ----------------
extern "C" void kernel_launch(void* const* d_in, const int* in_sizes, int n_in,
                              void* d_out, int out_size) {
    const float* x = (const float*)d_in[0];   // [256, 384]
    const float* y = (const float*)d_in[1];   // [32768, 384]
    float* out = (float*)d_out;               // [0]=loss, [1..]=transp

    __half *xh, *xl, *yh, *yl;
    float *xn, *yn;
    cudaGetSymbolAddress((void**)&xh, g_xh);
    cudaGetSymbolAddress((void**)&xl, g_xl);
    cudaGetSymbolAddress((void**)&yh, g_yh);
    cudaGetSymbolAddress((void**)&yl, g_yl);
    cudaGetSymbolAddress((void**)&xn, g_xn);
    cudaGetSymbolAddress((void**)&yn, g_yn);

    k_init<<<(Mm + 255) / 256, 256>>>(out);
    k_prep<<<Nn / 8, 256>>>(x, xh, xl, xn);
    k_prep<<<Mm / 8, 256>>>(y, yh, yl, yn);
    k_gemm_mma<<<dim3(Mm / 128, Nn / 128), 256>>>();
    k_sink<<<NB, NT>>>(out);
}